// round 15
// baseline (speedup 1.0000x reference)
#include <cuda_runtime.h>
#include <cuda_bf16.h>
#include <cfloat>
#include <math.h>
#include <stdint.h>

// ---------------------------------------------------------------------------
// VectorQuantizer: z (32,2048,256) f32, emb (1024,256) f32
// Output layout (float32):
//   [0] loss | [1..16777217) z_q | [16777217] perplexity
//   [16777218..+67108864) one-hot | [83886082..+65536) indices
// R15: R14 (occupancy-2 int8 design) with candidate coverage fixed:
// top-4 per thread over its 256-code span -> 16 candidates/row (stronger
// than the validated R6 config of top-2 per 128-code span). LIST_CAP 4096.
// Exact fp32 rescore byte-identical to the validated recipe.
// ---------------------------------------------------------------------------

#define NROWS   65536
#define CDIM    256
#define NE      1024

#define OFF_LOSS 0LL
#define OFF_ZQ   1LL
#define OFF_PERP 16777217LL
#define OFF_ENC  16777218LL
#define OFF_IDX  83886082LL

// quantization scales (validated R7/R9: bit-identical output)
#define SZ_F       19.5f
#define SE_F       130048.0f
#define SCALE_EN   1267968.0f           /* Sz*Se/2 */
#define MARGIN_I3  650                  /* ~4.1e-3 f32 */
#define LIST_CAP   4096

// ----- device scratch -----
__device__ uint4 g_eb4[NE * CDIM / 16];  // emb int8, row-major 256B/row
__device__ float g_enorm[NE];
__device__ int   g_enI[NE];
__device__ float g_part[256];
__device__ int   g_counts[NE];

// ======================= smem layout (bytes) ===============================
#define RST 272
#define SM_A       0                      // 256*272 = 69632
#define SM_B0      69632                  // 64*272 = 17408
#define SM_B1      87040                  // 17408 (end 104448)
#define SM_ENI     104448                 // 4096 int
#define SM_ZN      108544                 // 1024 f32
#define SM_TMP     109568                 // 2048 (512 norm partials; later idxs)
#define SM_CNT     111616                 // 16
#define SMEM_TC    111632
// aliases after mainloop:
#define SM_CAND    0                      // 256*16*4 = 16384   (in A)
#define SM_ROWRES  16384                  // 2048               (in A)
#define SM_HIST    18432                  // 4096               (in A)
#define SM_SBUF    22528                  // 8*1024 = 8192      (in A)
#define SM_RBUF    30720                  // 1024               (in A)
#define SM_LIST    69632                  // 4096*8 = 32768     (in B0+B1)

// ======================= PTX helpers =======================================
__device__ __forceinline__ uint32_t smem_u32(const void* p) {
    uint32_t a;
    asm("{ .reg .u64 t; cvta.to.shared.u64 t, %1; cvt.u32.u64 %0, t; }"
        : "=r"(a) : "l"(p));
    return a;
}
#define LDSM_X4(r0, r1, r2, r3, addr) \
    asm volatile("ldmatrix.sync.aligned.m8n8.x4.shared.b16 {%0,%1,%2,%3}, [%4];" \
                 : "=r"(r0), "=r"(r1), "=r"(r2), "=r"(r3) : "r"(addr))
#define MMAS8(c0, c1, c2, c3, a0, a1, a2, a3, b0, b1) \
    asm volatile("mma.sync.aligned.m16n8k32.row.col.s32.s8.s8.s32 " \
                 "{%0,%1,%2,%3}, {%4,%5,%6,%7}, {%8,%9}, {%0,%1,%2,%3};" \
                 : "+r"(c0), "+r"(c1), "+r"(c2), "+r"(c3) \
                 : "r"(a0), "r"(a1), "r"(a2), "r"(a3), "r"(b0), "r"(b1))
#define CP16(dst, src) \
    asm volatile("cp.async.cg.shared.global [%0], [%1], 16;" :: "r"(dst), "l"(src))
#define CP_COMMIT() asm volatile("cp.async.commit_group;" ::: "memory")
#define CP_WAIT0()  asm volatile("cp.async.wait_group 0;" ::: "memory")

// top-4 insert on packed u32 (score<<10 | idx), ascending; fast single-compare
// reject for the common case.
#define INS4U(b, u) do {                                              \
    if ((u) < (b)[3]) {                                               \
        if ((u) < (b)[1]) {                                           \
            if ((u) < (b)[0]) { (b)[3]=(b)[2]; (b)[2]=(b)[1]; (b)[1]=(b)[0]; (b)[0]=(u); } \
            else              { (b)[3]=(b)[2]; (b)[2]=(b)[1]; (b)[1]=(u); } \
        } else {                                                      \
            if ((u) < (b)[2]) { (b)[3]=(b)[2]; (b)[2]=(u); }          \
            else              { (b)[3]=(u); }                         \
        }                                                             \
    } } while (0)

__device__ __forceinline__ uint32_t packsi(int s, int idx) {
    return ((uint32_t)((s >> 3) + (1 << 20)) << 10) | (uint32_t)idx;
}
__device__ __forceinline__ uint32_t quant4(float x0, float x1, float x2, float x3,
                                           float sc) {
    int q0 = __float2int_rn(fminf(fmaxf(x0 * sc, -127.f), 127.f));
    int q1 = __float2int_rn(fminf(fmaxf(x1 * sc, -127.f), 127.f));
    int q2 = __float2int_rn(fminf(fmaxf(x2 * sc, -127.f), 127.f));
    int q3 = __float2int_rn(fminf(fmaxf(x3 * sc, -127.f), 127.f));
    return (q0 & 0xFF) | ((q1 & 0xFF) << 8) | ((q2 & 0xFF) << 16) | (q3 << 24);
}

// ---------------------------------------------------------------------------
// Prep (verbatim R9, validated): ||e||^2, int norm, int8 emb, counts zero.
// ---------------------------------------------------------------------------
__global__ void __launch_bounds__(256)
vq_prep(const float* __restrict__ emb) {
    int gw   = (blockIdx.x * blockDim.x + threadIdx.x) >> 5;
    int lane = threadIdx.x & 31;
    const float* e = emb + (size_t)gw * CDIM;
    float s = 0.f;
    #pragma unroll
    for (int i = lane; i < CDIM; i += 32) { float x = e[i]; s += x * x; }
    #pragma unroll
    for (int o = 16; o > 0; o >>= 1) s += __shfl_down_sync(0xffffffffu, s, o);
    if (lane == 0) {
        g_enorm[gw] = s;
        g_enI[gw] = __float2int_rn(s * SCALE_EN);
        g_counts[gw] = 0;
    }
    const float4* s4 = (const float4*)e;
    float4 a = s4[lane * 2], b = s4[lane * 2 + 1];
    uint2 pk;
    pk.x = quant4(a.x, a.y, a.z, a.w, SE_F);
    pk.y = quant4(b.x, b.y, b.z, b.w, SE_F);
    ((uint2*)g_eb4)[(size_t)gw * 32 + lane] = pk;
}

// Prefetch one 64-code int8 tile (16KB): 1024 chunks = 4 iters of 256 threads.
__device__ __forceinline__ void prefetch_B(uint32_t sdst, int ct, int tid) {
    const char* gsrc = (const char*)g_eb4 + (size_t)ct * 64 * 256;
    #pragma unroll
    for (int j = 0; j < 4; ++j) {
        int idx = tid + j * 256;              // 0..1023 chunks of 16B
        int row = idx >> 4, g = idx & 15;
        CP16(sdst + row * RST + g * 16, gsrc + row * 256 + g * 16);
    }
    CP_COMMIT();
}

// ---------------------------------------------------------------------------
// Fused main: 256 CTAs x 256 threads, occupancy 2. CTA = 256 rows x 1024.
// 8 warps, warp tile 32 rows x 64 codes; 16 iterations of 64-code B tiles.
// ---------------------------------------------------------------------------
__global__ void __launch_bounds__(256, 2)
vq_main_fused(const float* __restrict__ zf, const float* __restrict__ emb,
              float* __restrict__ out) {
    extern __shared__ char smem[];
    const uint32_t sb = smem_u32(smem);
    const int tid = threadIdx.x;
    const int lane = tid & 31, wid = tid >> 5;       // wid 0..7 = M-warp
    const int rowBase = blockIdx.x * 256;

    prefetch_B(sb + SM_B0, 0, tid);

    int*   enI = (int*)(smem + SM_ENI);
    float* zns = (float*)(smem + SM_ZN);
    float* tmp = (float*)(smem + SM_TMP);

    for (int i = tid; i < NE; i += 256) enI[i] = g_enI[i];

    // ---- A tile: validated half-row split recipe (R7), looped x2 ----
    #pragma unroll
    for (int h = 0; h < 2; ++h) {
        int t2 = tid + h * 256;
        int row = t2 >> 1, half = t2 & 1;
        const float4* zr = (const float4*)zf + ((size_t)(rowBase + row) * 64 + half * 32);
        char* arow = smem + SM_A + row * RST + half * 128;
        float s = 0.f;
        #pragma unroll 4
        for (int j = 0; j < 16; ++j) {
            float4 a = zr[2 * j], b = zr[2 * j + 1];
            s += a.x * a.x; s += a.y * a.y; s += a.z * a.z; s += a.w * a.w;
            s += b.x * b.x; s += b.y * b.y; s += b.z * b.z; s += b.w * b.w;
            uint2 pk;
            pk.x = quant4(a.x, a.y, a.z, a.w, SZ_F);
            pk.y = quant4(b.x, b.y, b.z, b.w, SZ_F);
            *(uint2*)(arow + j * 8) = pk;
        }
        tmp[t2] = s;
    }
    __syncthreads();
    zns[tid] = tmp[2 * tid] + tmp[2 * tid + 1];
    __syncthreads();

    int rloc[4];
    #pragma unroll
    for (int rs = 0; rs < 4; ++rs)
        rloc[rs] = wid * 32 + (rs >> 1) * 16 + (rs & 1) * 8 + (lane >> 2);

    uint32_t bu[4][4];
    #pragma unroll
    for (int rs = 0; rs < 4; ++rs)
        bu[rs][0] = bu[rs][1] = bu[rs][2] = bu[rs][3] = 0xFFFFFFFFu;

    // ldsm bases (validated R9 formulas; single N-warp group)
    const uint32_t aoff = sb + SM_A +
        (wid * 32 + (lane & 15)) * RST + (lane >> 4) * 16;
    const uint32_t boff =
        ((lane & 7) + ((lane >> 4) & 1) * 8) * RST + ((lane >> 3) & 1) * 16;

    for (int ct = 0; ct < 16; ++ct) {
        CP_WAIT0();
        __syncthreads();
        if (ct < 15) prefetch_B(sb + ((ct & 1) ? SM_B0 : SM_B1), ct + 1, tid);
        const uint32_t Bb = ((ct & 1) ? SM_B1 : SM_B0) + sb + boff;

        int c[2][8][4];
        #pragma unroll
        for (int mf = 0; mf < 2; ++mf)
            #pragma unroll
            for (int ng = 0; ng < 8; ++ng)
                #pragma unroll
                for (int q = 0; q < 4; ++q) c[mf][ng][q] = 0;

        #pragma unroll
        for (int kk = 0; kk < 8; ++kk) {
            uint32_t af[2][4];
            #pragma unroll
            for (int mf = 0; mf < 2; ++mf)
                LDSM_X4(af[mf][0], af[mf][1], af[mf][2], af[mf][3],
                        aoff + mf * 16 * RST + kk * 32);
            uint32_t bf[4][4];
            #pragma unroll
            for (int bl = 0; bl < 4; ++bl)
                LDSM_X4(bf[bl][0], bf[bl][1], bf[bl][2], bf[bl][3],
                        Bb + bl * 16 * RST + kk * 32);
            #pragma unroll
            for (int mf = 0; mf < 2; ++mf)
                #pragma unroll
                for (int bl = 0; bl < 4; ++bl) {
                    MMAS8(c[mf][bl*2][0], c[mf][bl*2][1], c[mf][bl*2][2], c[mf][bl*2][3],
                          af[mf][0], af[mf][1], af[mf][2], af[mf][3],
                          bf[bl][0], bf[bl][1]);
                    MMAS8(c[mf][bl*2+1][0], c[mf][bl*2+1][1], c[mf][bl*2+1][2], c[mf][bl*2+1][3],
                          af[mf][0], af[mf][1], af[mf][2], af[mf][3],
                          bf[bl][2], bf[bl][3]);
                }
        }

        // integer scoring + top-4 per row slot
        #pragma unroll
        for (int mf = 0; mf < 2; ++mf)
            #pragma unroll
            for (int ng = 0; ng < 8; ++ng) {
                const int n0 = ct * 64 + ng * 8 + (lane & 3) * 2;
                int2 ei = *(const int2*)&enI[n0];
                const int rsA = mf * 2, rsB = mf * 2 + 1;
                uint32_t u;
                u = packsi(ei.x - c[mf][ng][0], n0);     INS4U(bu[rsA], u);
                u = packsi(ei.y - c[mf][ng][1], n0 + 1); INS4U(bu[rsA], u);
                u = packsi(ei.x - c[mf][ng][2], n0);     INS4U(bu[rsB], u);
                u = packsi(ei.y - c[mf][ng][3], n0 + 1); INS4U(bu[rsB], u);
            }
    }
    __syncthreads();   // mainloop smem reads done before aliasing

    // ---- candidate merge + exact rescore ----------------------------------
    uint32_t* cand = (uint32_t*)(smem + SM_CAND);      // [256][16]
    unsigned long long* rowres = (unsigned long long*)(smem + SM_ROWRES);
    int2* list = (int2*)(smem + SM_LIST);
    int*  cnt  = (int*)(smem + SM_CNT);

    if (tid == 0) *cnt = 0;
    #pragma unroll
    for (int rs = 0; rs < 4; ++rs) {
        int slot = (lane & 3) * 4;
        cand[rloc[rs] * 16 + slot]     = bu[rs][0];
        cand[rloc[rs] * 16 + slot + 1] = bu[rs][1];
        cand[rloc[rs] * 16 + slot + 2] = bu[rs][2];
        cand[rloc[rs] * 16 + slot + 3] = bu[rs][3];
    }
    __syncthreads();

    {
        uint32_t best = cand[tid * 16];
        #pragma unroll
        for (int q = 1; q < 16; ++q) {
            uint32_t e = cand[tid * 16 + q];
            if (e < best) best = e;
        }
        int bsi = (int)(best >> 10);
        int nwithin = 0;
        #pragma unroll
        for (int q = 0; q < 16; ++q) {
            int si = (int)(cand[tid * 16 + q] >> 10);
            if (si - bsi <= MARGIN_I3) nwithin++;
        }
        if (nwithin <= 1) {
            rowres[tid] = (unsigned long long)(best & 1023u);
        } else {
            rowres[tid] = 0xFFFFFFFFFFFFFFFFULL;
            #pragma unroll
            for (int q = 0; q < 16; ++q) {
                uint32_t e = cand[tid * 16 + q];
                int si = (int)(e >> 10);
                if (si - bsi <= MARGIN_I3) {
                    int p = atomicAdd(cnt, 1);
                    if (p < LIST_CAP)
                        list[p] = make_int2(tid, (int)(e & 1023u));
                }
            }
        }
    }
    __syncthreads();

    // exact fp32 rescore: byte-identical to validated recipe
    int nc = *cnt; if (nc > LIST_CAP) nc = LIST_CAP;
    for (int i = tid; i < nc; i += 256) {
        int row = list[i].x, code = list[i].y;
        const float4* zr = (const float4*)(zf + (size_t)(rowBase + row) * CDIM);
        const float4* er = (const float4*)(emb + (size_t)code * CDIM);
        float lo = 0.f, hi = 0.f;
        #pragma unroll 4
        for (int k = 0; k < 64; ++k) {
            float4 a = zr[k], e4 = er[k];
            lo = fmaf(a.x, e4.x, lo);
            hi = fmaf(a.y, e4.y, hi);
            lo = fmaf(a.z, e4.z, lo);
            hi = fmaf(a.w, e4.w, hi);
        }
        float dot = lo + hi;
        float s = (zns[row] + g_enorm[code]) - 2.0f * dot;
        unsigned long long p =
            ((unsigned long long)__float_as_uint(s) << 32) | (unsigned)code;
        atomicMin(&rowres[row], p);
    }
    __syncthreads();

    // ---- finalize indices + fused epilogue --------------------------------
    int* idxs = (int*)(smem + SM_TMP);
    int* hist = (int*)(smem + SM_HIST);
    for (int i = tid; i < NE; i += 256) hist[i] = 0;
    __syncthreads();
    {
        int wi = (int)(rowres[tid] & 0xFFFFFFFFu);
        idxs[tid] = wi;
        out[OFF_IDX + rowBase + tid] = (float)wi;
        atomicAdd(&hist[wi], 1);
    }
    __syncthreads();

    // z_q + loss (warp-per-row, 32 rows/warp, staged in smem)
    float* sbuf = (float*)(smem + SM_SBUF) + wid * 256;
    float psum = 0.f;
    for (int rr = 0; rr < 32; ++rr) {
        const int row = wid * 32 + rr;
        const int idx = idxs[row];
        const float4* zr4 = (const float4*)zf + (size_t)(rowBase + row) * 64;
        const float4* er4 = (const float4*)emb + (size_t)idx * 64;
        #pragma unroll
        for (int it = 0; it < 2; ++it) {
            int k4 = it * 32 + lane;
            float4 a = zr4[k4], e = er4[k4];
            float dx = e.x - a.x, dy = e.y - a.y, dz = e.z - a.z, dw = e.w - a.w;
            psum += dx * dx + dy * dy + dz * dz + dw * dw;
            float4 q = {a.x + dx, a.y + dy, a.z + dz, a.w + dw};
            *(float4*)&sbuf[k4 * 4] = q;
        }
        __syncwarp();
        float* og = out + OFF_ZQ + (size_t)(rowBase + row) * 256;
        if (lane == 0) og[0] = sbuf[0];
        else if (lane == 1) { float2 t = {sbuf[1], sbuf[2]}; *(float2*)(og + 1) = t; }
        else if (lane == 2) og[255] = sbuf[255];
        #pragma unroll
        for (int c2 = lane; c2 < 63; c2 += 32) {
            int k = 3 + 4 * c2;
            float4 q = {sbuf[k], sbuf[k + 1], sbuf[k + 2], sbuf[k + 3]};
            *(float4*)(og + k) = q;
        }
        __syncwarp();
    }

    // one-hot rows (warp-per-row, f2 head/tail + f4 body, coalesced)
    for (int rr = 0; rr < 32; ++rr) {
        const int row = wid * 32 + rr;
        const int idx = idxs[row];
        float* og = out + OFF_ENC + (size_t)(rowBase + row) * 1024;
        if (lane == 0) {
            float2 t = {idx == 0 ? 1.f : 0.f, idx == 1 ? 1.f : 0.f};
            *(float2*)og = t;
        } else if (lane == 1) {
            float2 t = {idx == 1022 ? 1.f : 0.f, idx == 1023 ? 1.f : 0.f};
            *(float2*)(og + 1022) = t;
        }
        #pragma unroll
        for (int c2 = lane; c2 < 255; c2 += 32) {
            int k = 2 + 4 * c2;
            float4 v = {0.f, 0.f, 0.f, 0.f};
            unsigned d = (unsigned)(idx - k);
            if (d < 4u) {
                if (d == 0) v.x = 1.f;
                else if (d == 1) v.y = 1.f;
                else if (d == 2) v.z = 1.f;
                else v.w = 1.f;
            }
            *(float4*)(og + k) = v;
        }
    }

    // loss partial reduce + histogram flush
    float* rbuf = (float*)(smem + SM_RBUF);
    rbuf[tid] = psum;
    __syncthreads();
    #pragma unroll
    for (int s = 128; s > 0; s >>= 1) {
        if (tid < s) rbuf[tid] += rbuf[tid + s];
        __syncthreads();
    }
    if (tid == 0) g_part[blockIdx.x] = rbuf[0];
    for (int i = tid; i < NE; i += 256) {
        int h = hist[i];
        if (h) atomicAdd(&g_counts[i], h);
    }
}

// ---------------------------------------------------------------------------
__global__ void vq_finalize(float* __restrict__ out) {
    __shared__ double sd[256];
    int tid = threadIdx.x;
    sd[tid] = (double)g_part[tid];
    __syncthreads();
    #pragma unroll
    for (int st = 128; st > 0; st >>= 1) {
        if (tid < st) sd[tid] += sd[tid + st];
        __syncthreads();
    }
    if (tid == 0) {
        double mean = sd[0] / 16777216.0;
        out[OFF_LOSS] = (float)(mean + 0.25 * mean);
    }
    __syncthreads();
    double h = 0.0;
    for (int i = tid; i < NE; i += 256) {
        double m = (double)g_counts[i] / 65536.0;
        h += m * log(m + 1e-10);
    }
    sd[tid] = h;
    __syncthreads();
    #pragma unroll
    for (int st = 128; st > 0; st >>= 1) {
        if (tid < st) sd[tid] += sd[tid + st];
        __syncthreads();
    }
    if (tid == 0) out[OFF_PERP] = (float)exp(-sd[0]);
}

// ---------------------------------------------------------------------------
extern "C" void kernel_launch(void* const* d_in, const int* in_sizes, int n_in,
                              void* d_out, int out_size) {
    const float* z   = (const float*)d_in[0];
    const float* emb = (const float*)d_in[1];
    float* out = (float*)d_out;

    static int init_done = 0;
    if (!init_done) {
        cudaFuncSetAttribute(vq_main_fused,
                             cudaFuncAttributeMaxDynamicSharedMemorySize, SMEM_TC);
        init_done = 1;
    }

    vq_prep<<<128, 256>>>(emb);
    vq_main_fused<<<NROWS / 256, 256, SMEM_TC>>>(z, emb, out);
    vq_finalize<<<1, 256>>>(out);
}

// round 16
// speedup vs baseline: 1.2661x; 1.2661x over previous
#include <cuda_runtime.h>
#include <cuda_bf16.h>
#include <cfloat>
#include <math.h>
#include <stdint.h>

// ---------------------------------------------------------------------------
// VectorQuantizer: z (32,2048,256) f32, emb (1024,256) f32
// Output layout (float32):
//   [0] loss | [1..16777217) z_q | [16777217] perplexity
//   [16777218..+67108864) one-hot | [83886082..+65536) indices
// R16 == R6 verbatim (best measured: 246.1us, rel_err 3.737698e-07).
// bf16 HMMA mainloop (256-row CTA, 16 warps, 32x32 warp tiles, double-
// buffered 64-code B tiles, register-pipelined ldsm), per-row top-2
// candidates + exact fp32 rescore with reference-identical rounding,
// fully fused epilogue (one-hot, z_q, loss, histogram).
// ---------------------------------------------------------------------------

#define NROWS   65536
#define CDIM    256
#define NE      1024

#define OFF_LOSS 0LL
#define OFF_ZQ   1LL
#define OFF_PERP 16777217LL
#define OFF_ENC  16777218LL
#define OFF_IDX  83886082LL

#define MARGIN 1.5e-3f

// ----- device scratch -----
__device__ uint4 g_eb4[NE * CDIM / 8];      // emb as bf16 (row-major, 512KB)
__device__ float g_enorm[NE];
__device__ float g_part[256];
__device__ int   g_counts[NE];

// ======================= smem layout (bytes) ===============================
#define RST 528
#define SM_A       0                      // 256*528 = 135168
#define SM_B0      135168                 // 33792
#define SM_B1      168960                 // 33792 (end 202752)
#define SM_EN      202752                 // 4096
#define SM_ZN      206848                 // 1024
#define SM_CNT     207872                 // 16
#define SM_TMP     207888                 // 2048 (znorm partials, later idxs)
#define SMEM_TC    209936
// aliases in dead A region after mainloop:
#define SM_CAND    0                      // 32768
#define SM_LIST    32768                  // 32768
#define SM_ROWRES  65536                  // 2048
#define SM_HIST    67584                  // 4096
#define SM_RBUF    71680                  // 2048
#define SM_SBUF    73728                  // 16 warps * 1KB = 16384

// ======================= PTX helpers =======================================
__device__ __forceinline__ uint32_t smem_u32(const void* p) {
    uint32_t a;
    asm("{ .reg .u64 t; cvta.to.shared.u64 t, %1; cvt.u32.u64 %0, t; }"
        : "=r"(a) : "l"(p));
    return a;
}
#define LDSM_X4(r0, r1, r2, r3, addr) \
    asm volatile("ldmatrix.sync.aligned.m8n8.x4.shared.b16 {%0,%1,%2,%3}, [%4];" \
                 : "=r"(r0), "=r"(r1), "=r"(r2), "=r"(r3) : "r"(addr))
#define MMA16816(c0, c1, c2, c3, a0, a1, a2, a3, b0, b1) \
    asm volatile("mma.sync.aligned.m16n8k16.row.col.f32.bf16.bf16.f32 " \
                 "{%0,%1,%2,%3}, {%4,%5,%6,%7}, {%8,%9}, {%0,%1,%2,%3};" \
                 : "+f"(c0), "+f"(c1), "+f"(c2), "+f"(c3) \
                 : "r"(a0), "r"(a1), "r"(a2), "r"(a3), "r"(b0), "r"(b1))
#define CP16(dst, src) \
    asm volatile("cp.async.cg.shared.global [%0], [%1], 16;" :: "r"(dst), "l"(src))
#define CP_COMMIT() asm volatile("cp.async.commit_group;" ::: "memory")
#define CP_WAIT0()  asm volatile("cp.async.wait_group 0;" ::: "memory")

#define INS2(vv, jj, s, j) do {                                   \
    if ((s) < vv[1]) {                                            \
        if ((s) < vv[0]) { vv[1]=vv[0]; jj[1]=jj[0]; vv[0]=(s); jj[0]=(j); } \
        else             { vv[1]=(s); jj[1]=(j); }                \
    } } while (0)

// load all fragments for one kk into slot s
#define LD_FRAGS(s, kk) do {                                                    \
    LDSM_X4(Af[s][0], Af[s][1], Af[s][2], Af[s][3], aoff + (kk) * 32);          \
    LDSM_X4(Af[s][4], Af[s][5], Af[s][6], Af[s][7], aoff + 16 * RST + (kk) * 32); \
    LDSM_X4(Bf[s][0], Bf[s][1], Bf[s][2], Bf[s][3], Bb + (kk) * 32);            \
    LDSM_X4(Bf[s][4], Bf[s][5], Bf[s][6], Bf[s][7], Bb + 16 * RST + (kk) * 32); \
} while (0)

#define DO_MMAS(s) do {                                                          \
    MMA16816(c[0][0][0], c[0][0][1], c[0][0][2], c[0][0][3],                     \
             Af[s][0], Af[s][1], Af[s][2], Af[s][3], Bf[s][0], Bf[s][1]);        \
    MMA16816(c[0][1][0], c[0][1][1], c[0][1][2], c[0][1][3],                     \
             Af[s][0], Af[s][1], Af[s][2], Af[s][3], Bf[s][2], Bf[s][3]);        \
    MMA16816(c[0][2][0], c[0][2][1], c[0][2][2], c[0][2][3],                     \
             Af[s][0], Af[s][1], Af[s][2], Af[s][3], Bf[s][4], Bf[s][5]);        \
    MMA16816(c[0][3][0], c[0][3][1], c[0][3][2], c[0][3][3],                     \
             Af[s][0], Af[s][1], Af[s][2], Af[s][3], Bf[s][6], Bf[s][7]);        \
    MMA16816(c[1][0][0], c[1][0][1], c[1][0][2], c[1][0][3],                     \
             Af[s][4], Af[s][5], Af[s][6], Af[s][7], Bf[s][0], Bf[s][1]);        \
    MMA16816(c[1][1][0], c[1][1][1], c[1][1][2], c[1][1][3],                     \
             Af[s][4], Af[s][5], Af[s][6], Af[s][7], Bf[s][2], Bf[s][3]);        \
    MMA16816(c[1][2][0], c[1][2][1], c[1][2][2], c[1][2][3],                     \
             Af[s][4], Af[s][5], Af[s][6], Af[s][7], Bf[s][4], Bf[s][5]);        \
    MMA16816(c[1][3][0], c[1][3][1], c[1][3][2], c[1][3][3],                     \
             Af[s][4], Af[s][5], Af[s][6], Af[s][7], Bf[s][6], Bf[s][7]);        \
} while (0)

// ---------------------------------------------------------------------------
// Fused prep: zero histogram + ||e_j||^2 (verbatim R1 rounding) + bf16 pack.
// One warp per code, 1024 warps.
// ---------------------------------------------------------------------------
__global__ void __launch_bounds__(256)
vq_prep(const float* __restrict__ emb) {
    int gw   = (blockIdx.x * blockDim.x + threadIdx.x) >> 5;
    int lane = threadIdx.x & 31;
    const float* e = emb + (size_t)gw * CDIM;
    float s = 0.f;
    #pragma unroll
    for (int i = lane; i < CDIM; i += 32) { float x = e[i]; s += x * x; }
    #pragma unroll
    for (int o = 16; o > 0; o >>= 1) s += __shfl_down_sync(0xffffffffu, s, o);
    if (lane == 0) { g_enorm[gw] = s; g_counts[gw] = 0; }

    const float4* s4 = (const float4*)e;
    float4 a = s4[lane * 2], b = s4[lane * 2 + 1];
    __nv_bfloat162 h0 = __floats2bfloat162_rn(a.x, a.y);
    __nv_bfloat162 h1 = __floats2bfloat162_rn(a.z, a.w);
    __nv_bfloat162 h2 = __floats2bfloat162_rn(b.x, b.y);
    __nv_bfloat162 h3 = __floats2bfloat162_rn(b.z, b.w);
    uint4 pk;
    pk.x = *(uint32_t*)&h0; pk.y = *(uint32_t*)&h1;
    pk.z = *(uint32_t*)&h2; pk.w = *(uint32_t*)&h3;
    g_eb4[(size_t)gw * 32 + lane] = pk;
}

// Prefetch one 64-code bf16 tile into smem (padded rows) via cp.async.
__device__ __forceinline__ void prefetch_B(uint32_t sdst, int ct, int tid) {
    const char* gsrc = (const char*)g_eb4 + (size_t)ct * 64 * 512;
    #pragma unroll
    for (int j = 0; j < 4; ++j) {
        int idx = tid + j * 512;              // 0..2047
        int row = idx >> 5, g = idx & 31;
        CP16(sdst + row * RST + g * 16, gsrc + row * 512 + g * 16);
    }
    CP_COMMIT();
}

// ---------------------------------------------------------------------------
// Fused main: 256 CTAs x 512 threads. CTA = 256 rows x 1024 codes.
// Warp tile 32x32, register-double-buffered ldsm/MMA pipeline.
// ---------------------------------------------------------------------------
__global__ void __launch_bounds__(512, 1)
vq_main_fused(const float* __restrict__ zf, const float* __restrict__ emb,
              float* __restrict__ out) {
    extern __shared__ char smem[];
    const uint32_t sb = smem_u32(smem);
    const int tid = threadIdx.x;
    const int lane = tid & 31, wid = tid >> 5;
    const int mwarp = wid & 7, nwarp = wid >> 3;
    const int rowBase = blockIdx.x * 256;

    prefetch_B(sb + SM_B0, 0, tid);

    float* ens = (float*)(smem + SM_EN);
    float* zns = (float*)(smem + SM_ZN);
    float* tmp = (float*)(smem + SM_TMP);

    for (int i = tid; i < NE; i += 512) ens[i] = g_enorm[i];

    // ---- A tile: load z f32, convert to bf16 (padded smem), norm partials
    {
        int row = tid >> 1, half = tid & 1;
        const float4* zr = (const float4*)zf + ((size_t)(rowBase + row) * 64 + half * 32);
        char* arow = smem + SM_A + row * RST + half * 256;
        float s = 0.f;
        #pragma unroll 4
        for (int j = 0; j < 16; ++j) {
            float4 a = zr[2 * j], b = zr[2 * j + 1];
            s += a.x * a.x; s += a.y * a.y; s += a.z * a.z; s += a.w * a.w;
            s += b.x * b.x; s += b.y * b.y; s += b.z * b.z; s += b.w * b.w;
            __nv_bfloat162 h0 = __floats2bfloat162_rn(a.x, a.y);
            __nv_bfloat162 h1 = __floats2bfloat162_rn(a.z, a.w);
            __nv_bfloat162 h2 = __floats2bfloat162_rn(b.x, b.y);
            __nv_bfloat162 h3 = __floats2bfloat162_rn(b.z, b.w);
            uint4 pk;
            pk.x = *(uint32_t*)&h0; pk.y = *(uint32_t*)&h1;
            pk.z = *(uint32_t*)&h2; pk.w = *(uint32_t*)&h3;
            *(uint4*)(arow + j * 16) = pk;
        }
        tmp[tid] = s;
    }
    __syncthreads();
    if (tid < 256) zns[tid] = tmp[2 * tid] + tmp[2 * tid + 1];
    __syncthreads();

    int rloc[4]; float zn[4];
    #pragma unroll
    for (int rs = 0; rs < 4; ++rs) {
        rloc[rs] = mwarp * 32 + (rs >> 1) * 16 + (rs & 1) * 8 + (lane >> 2);
        zn[rs] = zns[rloc[rs]];
    }

    float bv[4][2]; int bj[4][2];
    #pragma unroll
    for (int rs = 0; rs < 4; ++rs) { bv[rs][0] = bv[rs][1] = FLT_MAX; bj[rs][0] = bj[rs][1] = 0; }

    const uint32_t aoff = sb + SM_A +
        (mwarp * 32 + (lane & 7) + ((lane >> 3) & 1) * 8) * RST + (lane >> 4) * 16;
    const uint32_t boff =
        (nwarp * 32 + (lane & 7) + ((lane >> 4) & 1) * 8) * RST + ((lane >> 3) & 1) * 16;

    for (int ct = 0; ct < 16; ++ct) {
        CP_WAIT0();
        __syncthreads();
        if (ct < 15) prefetch_B(sb + ((ct & 1) ? SM_B0 : SM_B1), ct + 1, tid);
        const uint32_t Bb = ((ct & 1) ? SM_B1 : SM_B0) + sb + boff;

        float c[2][4][4];
        #pragma unroll
        for (int t = 0; t < 2; ++t)
            #pragma unroll
            for (int g = 0; g < 4; ++g)
                #pragma unroll
                for (int q = 0; q < 4; ++q) c[t][g][q] = 0.f;

        uint32_t Af[2][8], Bf[2][8];
        LD_FRAGS(0, 0);
        #pragma unroll
        for (int kk = 0; kk < 16; kk += 2) {
            if (kk + 1 < 16) LD_FRAGS(1, kk + 1);
            DO_MMAS(0);
            if (kk + 2 < 16) LD_FRAGS(0, kk + 2);
            DO_MMAS(1);
        }

        #pragma unroll
        for (int t = 0; t < 2; ++t)
            #pragma unroll
            for (int g = 0; g < 4; ++g) {
                const int n0 = ct * 64 + nwarp * 32 + g * 8 + (lane & 3) * 2;
                const float e0 = ens[n0], e1 = ens[n0 + 1];
                const int rsA = t * 2, rsB = t * 2 + 1;
                float s;
                s = fmaf(-2.0f, c[t][g][0], zn[rsA] + e0); INS2(bv[rsA], bj[rsA], s, n0);
                s = fmaf(-2.0f, c[t][g][1], zn[rsA] + e1); INS2(bv[rsA], bj[rsA], s, n0 + 1);
                s = fmaf(-2.0f, c[t][g][2], zn[rsB] + e0); INS2(bv[rsB], bj[rsB], s, n0);
                s = fmaf(-2.0f, c[t][g][3], zn[rsB] + e1); INS2(bv[rsB], bj[rsB], s, n0 + 1);
            }
    }
    __syncthreads();   // all ldsm/A reads done before aliasing A region

    // ---- candidate merge + exact rescore (aliased onto dead A region) -----
    unsigned long long* cand   = (unsigned long long*)(smem + SM_CAND);
    unsigned long long* rowres = (unsigned long long*)(smem + SM_ROWRES);
    int2* list = (int2*)(smem + SM_LIST);
    int*  cnt  = (int*)(smem + SM_CNT);

    if (tid == 0) *cnt = 0;
    #pragma unroll
    for (int rs = 0; rs < 4; ++rs) {
        int slot = (nwarp * 4 + (lane & 3)) * 2;
        cand[rloc[rs] * 16 + slot] =
            ((unsigned long long)__float_as_uint(bv[rs][0]) << 32) | (unsigned)bj[rs][0];
        cand[rloc[rs] * 16 + slot + 1] =
            ((unsigned long long)__float_as_uint(bv[rs][1]) << 32) | (unsigned)bj[rs][1];
    }
    __syncthreads();

    if (tid < 256) {
        unsigned long long best = cand[tid * 16];
        #pragma unroll
        for (int q = 1; q < 16; ++q) {
            unsigned long long e = cand[tid * 16 + q];
            if (e < best) best = e;
        }
        float bvv = __uint_as_float((uint32_t)(best >> 32));
        float thr = bvv + MARGIN;
        int nwithin = 0;
        #pragma unroll
        for (int q = 0; q < 16; ++q) {
            float v = __uint_as_float((uint32_t)(cand[tid * 16 + q] >> 32));
            if (v <= thr) nwithin++;
        }
        if (nwithin <= 1) {
            rowres[tid] = best;
        } else {
            rowres[tid] = 0xFFFFFFFFFFFFFFFFULL;
            #pragma unroll
            for (int q = 0; q < 16; ++q) {
                unsigned long long e = cand[tid * 16 + q];
                float v = __uint_as_float((uint32_t)(e >> 32));
                if (v <= thr) {
                    int p = atomicAdd(cnt, 1);
                    list[p] = make_int2(tid, (int)(e & 0xFFFFFFFFu));
                }
            }
        }
    }
    __syncthreads();

    int nc = *cnt;
    for (int i = tid; i < nc; i += 512) {
        int row = list[i].x, code = list[i].y;
        const float4* zr = (const float4*)(zf + (size_t)(rowBase + row) * CDIM);
        const float4* er = (const float4*)(emb + (size_t)code * CDIM);
        float lo = 0.f, hi = 0.f;
        #pragma unroll 4
        for (int k = 0; k < 64; ++k) {
            float4 a = zr[k], e4 = er[k];
            lo = fmaf(a.x, e4.x, lo);
            hi = fmaf(a.y, e4.y, hi);
            lo = fmaf(a.z, e4.z, lo);
            hi = fmaf(a.w, e4.w, hi);
        }
        float dot = lo + hi;
        float s = (zns[row] + ens[code]) - 2.0f * dot;
        unsigned long long p =
            ((unsigned long long)__float_as_uint(s) << 32) | (unsigned)code;
        atomicMin(&rowres[row], p);
    }
    __syncthreads();

    // ---- finalize indices + fused epilogue ----
    int* idxs = (int*)(smem + SM_TMP);
    int* hist = (int*)(smem + SM_HIST);
    for (int i = tid; i < NE; i += 512) hist[i] = 0;
    __syncthreads();
    if (tid < 256) {
        int wi = (int)(rowres[tid] & 0xFFFFFFFFu);
        idxs[tid] = wi;
        out[OFF_IDX + rowBase + tid] = (float)wi;
        atomicAdd(&hist[wi], 1);
    }
    __syncthreads();

    // z_q + loss (warp-per-row, staged in smem for aligned stores)
    float* sbuf = (float*)(smem + SM_SBUF) + wid * 256;
    float psum = 0.f;
    for (int rr = 0; rr < 16; ++rr) {
        const int row = wid * 16 + rr;
        const int idx = idxs[row];
        const float4* zr4 = (const float4*)zf + (size_t)(rowBase + row) * 64;
        const float4* er4 = (const float4*)emb + (size_t)idx * 64;
        #pragma unroll
        for (int it = 0; it < 2; ++it) {
            int k4 = it * 32 + lane;
            float4 a = zr4[k4], e = er4[k4];
            float dx = e.x - a.x, dy = e.y - a.y, dz = e.z - a.z, dw = e.w - a.w;
            psum += dx * dx + dy * dy + dz * dz + dw * dw;
            float4 q = {a.x + dx, a.y + dy, a.z + dz, a.w + dw};
            *(float4*)&sbuf[k4 * 4] = q;
        }
        __syncwarp();
        float* og = out + OFF_ZQ + (size_t)(rowBase + row) * 256;
        if (lane == 0) og[0] = sbuf[0];
        else if (lane == 1) { float2 t = {sbuf[1], sbuf[2]}; *(float2*)(og + 1) = t; }
        else if (lane == 2) og[255] = sbuf[255];
        #pragma unroll
        for (int c2 = lane; c2 < 63; c2 += 32) {
            int k = 3 + 4 * c2;
            float4 q = {sbuf[k], sbuf[k + 1], sbuf[k + 2], sbuf[k + 3]};
            *(float4*)(og + k) = q;
        }
        __syncwarp();
    }

    // one-hot rows (warp-per-row, f2 head/tail + f4 body, coalesced)
    for (int rr = 0; rr < 16; ++rr) {
        const int row = wid * 16 + rr;
        const int idx = idxs[row];
        float* og = out + OFF_ENC + (size_t)(rowBase + row) * 1024;
        if (lane == 0) {
            float2 t = {idx == 0 ? 1.f : 0.f, idx == 1 ? 1.f : 0.f};
            *(float2*)og = t;
        } else if (lane == 1) {
            float2 t = {idx == 1022 ? 1.f : 0.f, idx == 1023 ? 1.f : 0.f};
            *(float2*)(og + 1022) = t;
        }
        #pragma unroll
        for (int c2 = lane; c2 < 255; c2 += 32) {
            int k = 2 + 4 * c2;
            float4 v = {0.f, 0.f, 0.f, 0.f};
            unsigned d = (unsigned)(idx - k);
            if (d < 4u) {
                if (d == 0) v.x = 1.f;
                else if (d == 1) v.y = 1.f;
                else if (d == 2) v.z = 1.f;
                else v.w = 1.f;
            }
            *(float4*)(og + k) = v;
        }
    }

    // loss partial reduce + histogram flush
    float* rbuf = (float*)(smem + SM_RBUF);
    rbuf[tid] = psum;
    __syncthreads();
    #pragma unroll
    for (int s = 256; s > 0; s >>= 1) {
        if (tid < s) rbuf[tid] += rbuf[tid + s];
        __syncthreads();
    }
    if (tid == 0) g_part[blockIdx.x] = rbuf[0];
    for (int i = tid; i < NE; i += 512) {
        int h = hist[i];
        if (h) atomicAdd(&g_counts[i], h);
    }
}

// ---------------------------------------------------------------------------
__global__ void vq_finalize(float* __restrict__ out) {
    __shared__ double sd[256];
    int tid = threadIdx.x;
    sd[tid] = (double)g_part[tid];
    __syncthreads();
    #pragma unroll
    for (int st = 128; st > 0; st >>= 1) {
        if (tid < st) sd[tid] += sd[tid + st];
        __syncthreads();
    }
    if (tid == 0) {
        double mean = sd[0] / 16777216.0;
        out[OFF_LOSS] = (float)(mean + 0.25 * mean);
    }
    __syncthreads();
    double h = 0.0;
    for (int i = tid; i < NE; i += 256) {
        double m = (double)g_counts[i] / 65536.0;
        h += m * log(m + 1e-10);
    }
    sd[tid] = h;
    __syncthreads();
    #pragma unroll
    for (int st = 128; st > 0; st >>= 1) {
        if (tid < st) sd[tid] += sd[tid + st];
        __syncthreads();
    }
    if (tid == 0) out[OFF_PERP] = (float)exp(-sd[0]);
}

// ---------------------------------------------------------------------------
extern "C" void kernel_launch(void* const* d_in, const int* in_sizes, int n_in,
                              void* d_out, int out_size) {
    const float* z   = (const float*)d_in[0];
    const float* emb = (const float*)d_in[1];
    float* out = (float*)d_out;

    static int init_done = 0;
    if (!init_done) {
        cudaFuncSetAttribute(vq_main_fused,
                             cudaFuncAttributeMaxDynamicSharedMemorySize, SMEM_TC);
        init_done = 1;
    }

    vq_prep<<<128, 256>>>(emb);
    vq_main_fused<<<NROWS / 256, 512, SMEM_TC>>>(z, emb, out);
    vq_finalize<<<1, 256>>>(out);
}